// round 1
// baseline (speedup 1.0000x reference)
#include <cuda_runtime.h>
#include <math.h>

#define BB 2
#define TT 2048
#define CC 1024
#define HH 16
#define HS 64
#define BT (BB*TT)   // 4096

// Scratch (no allocations allowed)
__device__ float g_qkv[(size_t)BT * 3 * CC];  // [4096][3072]
__device__ float g_att[(size_t)BT * CC];      // [4096][1024]

// ---------------------------------------------------------------------------
// GEMM: Cmat[M,N] = A[M,K] @ W[N,K]^T (+ bias). Tiles 64x64x16, 256 thr, 4x4.
// ---------------------------------------------------------------------------
__global__ __launch_bounds__(256)
void gemm_nt(const float* __restrict__ A, const float* __restrict__ W,
             const float* __restrict__ bias, float* __restrict__ Cmat,
             int N, int K, int hasBias) {
    __shared__ float As[16][65];  // [k][m], padded
    __shared__ float Ws[16][65];  // [k][n], padded
    const int tid = threadIdx.x;
    const int tx = tid & 15, ty = tid >> 4;
    const int bm = blockIdx.y * 64, bn = blockIdx.x * 64;
    const int idx = tid * 4;
    const int m  = idx >> 4;     // 0..63
    const int kk = idx & 15;     // 0,4,8,12

    float acc[4][4] = {};

    for (int k0 = 0; k0 < K; k0 += 16) {
        float4 va = *reinterpret_cast<const float4*>(&A[(size_t)(bm + m) * K + k0 + kk]);
        float4 vw = *reinterpret_cast<const float4*>(&W[(size_t)(bn + m) * K + k0 + kk]);
        __syncthreads();  // previous compute done before overwrite
        As[kk + 0][m] = va.x; As[kk + 1][m] = va.y; As[kk + 2][m] = va.z; As[kk + 3][m] = va.w;
        Ws[kk + 0][m] = vw.x; Ws[kk + 1][m] = vw.y; Ws[kk + 2][m] = vw.z; Ws[kk + 3][m] = vw.w;
        __syncthreads();
        #pragma unroll
        for (int kq = 0; kq < 16; kq++) {
            float a[4], b[4];
            #pragma unroll
            for (int i = 0; i < 4; i++) a[i] = As[kq][ty * 4 + i];
            #pragma unroll
            for (int j = 0; j < 4; j++) b[j] = Ws[kq][tx * 4 + j];
            #pragma unroll
            for (int i = 0; i < 4; i++)
                #pragma unroll
                for (int j = 0; j < 4; j++)
                    acc[i][j] = fmaf(a[i], b[j], acc[i][j]);
        }
    }

    #pragma unroll
    for (int i = 0; i < 4; i++) {
        const size_t row = (size_t)(bm + ty * 4 + i) * N;
        #pragma unroll
        for (int j = 0; j < 4; j++) {
            const int n = bn + tx * 4 + j;
            float v = acc[i][j];
            if (hasBias) v += bias[n];
            Cmat[row + n] = v;
        }
    }
}

// ---------------------------------------------------------------------------
// sp2norm attention, single pass over key blocks (causal).
// grid: (T/64, H, B), block: 256 threads, dynamic smem.
// smem: Qs[d][q] 64x64, Ks[d][k] 64x64, Vs[k][d] 64x64, Wt[k][q] 64x65, rowsq[64]
// ---------------------------------------------------------------------------
#define ATTN_SMEM_FLOATS (3 * 4096 + 64 * 65 + 64)
#define ATTN_SMEM_BYTES  (ATTN_SMEM_FLOATS * 4)

__global__ __launch_bounds__(256)
void attn_kernel(const float* __restrict__ qkv, float* __restrict__ att) {
    extern __shared__ float sm[];
    float* Qs    = sm;                 // [d*64 + q]
    float* Ks    = Qs + 4096;          // [d*64 + k]
    float* Vs    = Ks + 4096;          // [k*64 + d]
    float* Wt    = Vs + 4096;          // [k*65 + q]
    float* rowsq = Wt + 64 * 65;       // [64]

    const int tid = threadIdx.x;
    const int tx = tid & 15, ty = tid >> 4;
    const int qb = blockIdx.x, h = blockIdx.y, b = blockIdx.z;
    const size_t rowbase = (size_t)b * TT * (3 * CC);
    const float scale = 0.125f;  // 1/sqrt(64)

    // Load Q tile transposed: Qs[d][q]
    #pragma unroll
    for (int r = 0; r < 4; r++) {
        int idx = (tid + r * 256) * 4;
        int qi = idx >> 6, d = idx & 63;
        float4 v = *reinterpret_cast<const float4*>(
            &qkv[rowbase + (size_t)(qb * 64 + qi) * (3 * CC) + h * HS + d]);
        Qs[(d + 0) * 64 + qi] = v.x;
        Qs[(d + 1) * 64 + qi] = v.y;
        Qs[(d + 2) * 64 + qi] = v.z;
        Qs[(d + 3) * 64 + qi] = v.w;
    }
    if (tid < 64) rowsq[tid] = 0.f;

    float o[4][4] = {};

    for (int j = 0; j <= qb; j++) {
        __syncthreads();  // previous Wt/Vs reads complete; first iter: Q stores before reads
        // Load K (transposed) and V (natural)
        #pragma unroll
        for (int r = 0; r < 4; r++) {
            int idx = (tid + r * 256) * 4;
            int ki = idx >> 6, d = idx & 63;
            size_t base = rowbase + (size_t)(j * 64 + ki) * (3 * CC) + h * HS + d;
            float4 kv = *reinterpret_cast<const float4*>(&qkv[base + CC]);
            Ks[(d + 0) * 64 + ki] = kv.x;
            Ks[(d + 1) * 64 + ki] = kv.y;
            Ks[(d + 2) * 64 + ki] = kv.z;
            Ks[(d + 3) * 64 + ki] = kv.w;
            float4 vv = *reinterpret_cast<const float4*>(&qkv[base + 2 * CC]);
            *reinterpret_cast<float4*>(&Vs[ki * 64 + d]) = vv;
        }
        __syncthreads();

        // S = Q K^T (4x4 per thread)
        float s[4][4] = {};
        #pragma unroll 8
        for (int d = 0; d < 64; d++) {
            float a[4], bq[4];
            #pragma unroll
            for (int i = 0; i < 4; i++) a[i] = Qs[d * 64 + ty * 4 + i];
            #pragma unroll
            for (int jj = 0; jj < 4; jj++) bq[jj] = Ks[d * 64 + tx * 4 + jj];
            #pragma unroll
            for (int i = 0; i < 4; i++)
                #pragma unroll
                for (int jj = 0; jj < 4; jj++)
                    s[i][jj] = fmaf(a[i], bq[jj], s[i][jj]);
        }

        // softplus + causal mask + rowsq partial + store W transposed
        const bool diag = (j == qb);
        #pragma unroll
        for (int i = 0; i < 4; i++) {
            const int qg = qb * 64 + ty * 4 + i;
            float p = 0.f;
            #pragma unroll
            for (int jj = 0; jj < 4; jj++) {
                const int kg = j * 64 + tx * 4 + jj;
                float sv = s[i][jj] * scale;
                float w = fmaxf(sv, 0.f) + log1pf(__expf(-fabsf(sv)));
                if (diag && kg > qg) w = 0.f;
                p = fmaf(w, w, p);
                Wt[(tx * 4 + jj) * 65 + ty * 4 + i] = w;
            }
            // reduce across the 16 tx lanes (lanes form contiguous 16-lane groups)
            p += __shfl_down_sync(0xffffffffu, p, 8, 16);
            p += __shfl_down_sync(0xffffffffu, p, 4, 16);
            p += __shfl_down_sync(0xffffffffu, p, 2, 16);
            p += __shfl_down_sync(0xffffffffu, p, 1, 16);
            if (tx == 0) rowsq[ty * 4 + i] += p;
        }
        __syncthreads();

        // O += W @ V : o[q][d] += sum_k Wt[k][q] * Vs[k][d]
        #pragma unroll 8
        for (int kk = 0; kk < 64; kk++) {
            float a[4], bv[4];
            #pragma unroll
            for (int i = 0; i < 4; i++) a[i] = Wt[kk * 65 + ty * 4 + i];
            #pragma unroll
            for (int jj = 0; jj < 4; jj++) bv[jj] = Vs[kk * 64 + tx * 4 + jj];
            #pragma unroll
            for (int i = 0; i < 4; i++)
                #pragma unroll
                for (int jj = 0; jj < 4; jj++)
                    o[i][jj] = fmaf(a[i], bv[jj], o[i][jj]);
        }
    }

    // Normalize and write back in [B,T,C] layout (head h occupies cols h*64..)
    #pragma unroll
    for (int i = 0; i < 4; i++) {
        const int qg = qb * 64 + ty * 4 + i;
        const float inv = rsqrtf(rowsq[ty * 4 + i]);
        #pragma unroll
        for (int jj = 0; jj < 4; jj++) {
            att[(size_t)(b * TT + qg) * CC + h * HS + tx * 4 + jj] = o[i][jj] * inv;
        }
    }
}

// ---------------------------------------------------------------------------
extern "C" void kernel_launch(void* const* d_in, const int* in_sizes, int n_in,
                              void* d_out, int out_size) {
    const float* x     = (const float*)d_in[0];  // [2,2048,1024]
    const float* Wqkv  = (const float*)d_in[1];  // [3072,1024]
    const float* Wproj = (const float*)d_in[2];  // [1024,1024]
    const float* bproj = (const float*)d_in[3];  // [1024]
    float* out = (float*)d_out;

    float *qkvp = nullptr, *attp = nullptr;
    cudaGetSymbolAddress((void**)&qkvp, g_qkv);
    cudaGetSymbolAddress((void**)&attp, g_att);

    cudaFuncSetAttribute(attn_kernel, cudaFuncAttributeMaxDynamicSharedMemorySize,
                         ATTN_SMEM_BYTES);

    // 1) QKV = x @ Wqkv^T : [4096,3072]
    gemm_nt<<<dim3((3 * CC) / 64, BT / 64), 256>>>(x, Wqkv, nullptr, qkvp, 3 * CC, CC, 0);

    // 2) attention (causal sp2norm) -> [4096,1024] in [B,T,C] layout
    attn_kernel<<<dim3(TT / 64, HH, BB), 256, ATTN_SMEM_BYTES>>>(qkvp, attp);

    // 3) out = att @ Wproj^T + b
    gemm_nt<<<dim3(CC / 64, BT / 64), 256>>>(attp, Wproj, bproj, out, CC, CC, 1);
}

// round 2
// speedup vs baseline: 1.4570x; 1.4570x over previous
#include <cuda_runtime.h>
#include <math.h>

#define BB 2
#define TT 2048
#define CC 1024
#define HH 16
#define HS 64
#define BT (BB*TT)   // 4096

typedef unsigned long long u64;

__device__ __forceinline__ u64 pk2(float x, float y) {
    u64 r; asm("mov.b64 %0, {%1,%2};" : "=l"(r) : "f"(x), "f"(y)); return r;
}
__device__ __forceinline__ void upk2(u64 v, float& x, float& y) {
    asm("mov.b64 {%0,%1}, %2;" : "=f"(x), "=f"(y) : "l"(v));
}
__device__ __forceinline__ void ffma2(u64& d, u64 a, u64 b) {
    asm("fma.rn.f32x2 %0, %1, %2, %0;" : "+l"(d) : "l"(a), "l"(b));
}

// Scratch (no allocations allowed)
__device__ float g_qkv[(size_t)BT * 3 * CC];  // [4096][3072]
__device__ float g_att[(size_t)BT * CC];      // [4096][1024]

// ---------------------------------------------------------------------------
// GEMM: C[M,N] = A[M,K] @ W[N,K]^T (+bias). 128x128x16 tile, 256 thr, 8x8
// microtile, packed f32x2 FMAs. Smem [k][m] transposed, stride 132.
// ---------------------------------------------------------------------------
__global__ __launch_bounds__(256, 2)
void gemm_nt(const float* __restrict__ A, const float* __restrict__ W,
             const float* __restrict__ bias, float* __restrict__ Cmat,
             int N, int K, int hasBias) {
    __shared__ float As[16][132];
    __shared__ float Ws[16][132];
    const int tid = threadIdx.x;
    const int tx = tid & 15, ty = tid >> 4;
    const int bm = blockIdx.y * 128, bn = blockIdx.x * 128;
    const int lr = tid >> 2;          // 0..63
    const int lc = (tid & 3) * 4;     // 0,4,8,12

    const float* Ap = A + (size_t)(bm + lr) * K + lc;
    const float* Wp = W + (size_t)(bn + lr) * K + lc;

    u64 acc[8][4];
    #pragma unroll
    for (int i = 0; i < 8; i++)
        #pragma unroll
        for (int j = 0; j < 4; j++) acc[i][j] = 0ull;

    for (int k0 = 0; k0 < K; k0 += 16) {
        float4 a0 = *(const float4*)(Ap);
        float4 a1 = *(const float4*)(Ap + (size_t)64 * K);
        float4 w0 = *(const float4*)(Wp);
        float4 w1 = *(const float4*)(Wp + (size_t)64 * K);
        __syncthreads();
        As[lc + 0][lr] = a0.x; As[lc + 1][lr] = a0.y; As[lc + 2][lr] = a0.z; As[lc + 3][lr] = a0.w;
        As[lc + 0][lr + 64] = a1.x; As[lc + 1][lr + 64] = a1.y; As[lc + 2][lr + 64] = a1.z; As[lc + 3][lr + 64] = a1.w;
        Ws[lc + 0][lr] = w0.x; Ws[lc + 1][lr] = w0.y; Ws[lc + 2][lr] = w0.z; Ws[lc + 3][lr] = w0.w;
        Ws[lc + 0][lr + 64] = w1.x; Ws[lc + 1][lr + 64] = w1.y; Ws[lc + 2][lr + 64] = w1.z; Ws[lc + 3][lr + 64] = w1.w;
        __syncthreads();
        #pragma unroll
        for (int kq = 0; kq < 16; kq++) {
            float4 af0 = *(const float4*)&As[kq][ty * 8];
            float4 af1 = *(const float4*)&As[kq][ty * 8 + 4];
            float4 bf0 = *(const float4*)&Ws[kq][tx * 8];
            float4 bf1 = *(const float4*)&Ws[kq][tx * 8 + 4];
            u64 b2[4] = { pk2(bf0.x, bf0.y), pk2(bf0.z, bf0.w),
                          pk2(bf1.x, bf1.y), pk2(bf1.z, bf1.w) };
            float av[8] = {af0.x, af0.y, af0.z, af0.w, af1.x, af1.y, af1.z, af1.w};
            #pragma unroll
            for (int i = 0; i < 8; i++) {
                u64 a2 = pk2(av[i], av[i]);
                #pragma unroll
                for (int j = 0; j < 4; j++) ffma2(acc[i][j], a2, b2[j]);
            }
        }
        Ap += 16; Wp += 16;
    }

    const int n0 = bn + tx * 8;
    float bv[8];
    if (hasBias) {
        float4 q0 = *(const float4*)&bias[n0];
        float4 q1 = *(const float4*)&bias[n0 + 4];
        bv[0] = q0.x; bv[1] = q0.y; bv[2] = q0.z; bv[3] = q0.w;
        bv[4] = q1.x; bv[5] = q1.y; bv[6] = q1.z; bv[7] = q1.w;
    } else {
        #pragma unroll
        for (int u = 0; u < 8; u++) bv[u] = 0.f;
    }
    #pragma unroll
    for (int i = 0; i < 8; i++) {
        const size_t row = (size_t)(bm + ty * 8 + i) * N;
        float c[8];
        #pragma unroll
        for (int j = 0; j < 4; j++) upk2(acc[i][j], c[2 * j], c[2 * j + 1]);
        #pragma unroll
        for (int u = 0; u < 8; u++) c[u] += bv[u];
        *(float4*)&Cmat[row + n0]     = make_float4(c[0], c[1], c[2], c[3]);
        *(float4*)&Cmat[row + n0 + 4] = make_float4(c[4], c[5], c[6], c[7]);
    }
}

// ---------------------------------------------------------------------------
// sp2norm attention: Br=128, Bc=64, 256 thr, 8x4 microtile, packed f32x2.
// Qs [d][q] stride 132 (pre-scaled), Ks [d][k^swz] stride 64, Vs [k][d],
// Wt [q][k] stride 68. rowsq kept in registers, shuffle-reduced at the end.
// ---------------------------------------------------------------------------
#define QS_SZ (64 * 132)
#define KS_SZ (64 * 64)
#define VS_SZ (64 * 64)
#define WT_SZ (128 * 68)
#define ATTN_SMEM_BYTES ((QS_SZ + KS_SZ + VS_SZ + WT_SZ) * 4)

__global__ __launch_bounds__(256, 2)
void attn_kernel(const float* __restrict__ qkv, float* __restrict__ att) {
    extern __shared__ float sm[];
    float* Qs = sm;             // [d*132 + q]
    float* Ks = Qs + QS_SZ;     // [d*64 + (k ^ (d&60))]
    float* Vs = Ks + KS_SZ;     // [k*64 + d]
    float* Wt = Vs + VS_SZ;     // [q*68 + k]

    const int tid = threadIdx.x;
    const int tx = tid & 15, ty = tid >> 4;
    const int qb = gridDim.x - 1 - blockIdx.x;   // big tiles first
    const int h = blockIdx.y, b = blockIdx.z;
    const size_t base = (size_t)b * TT * (3 * CC) + h * HS;

    // Load Q tile [128 x 64] transposed & pre-scaled by 1/sqrt(hs)
    #pragma unroll
    for (int r = 0; r < 8; r++) {
        int f4 = tid + r * 256;          // 0..2047
        int q = f4 >> 4;                 // 0..127
        int d = (f4 & 15) * 4;
        float4 v = *(const float4*)&qkv[base + (size_t)(qb * 128 + q) * (3 * CC) + d];
        Qs[(d + 0) * 132 + q] = v.x * 0.125f;
        Qs[(d + 1) * 132 + q] = v.y * 0.125f;
        Qs[(d + 2) * 132 + q] = v.z * 0.125f;
        Qs[(d + 3) * 132 + q] = v.w * 0.125f;
    }

    u64 o2[8][2];
    float prsq[8];
    #pragma unroll
    for (int i = 0; i < 8; i++) { o2[i][0] = 0ull; o2[i][1] = 0ull; prsq[i] = 0.f; }

    const int jmax = 2 * qb + 1;
    for (int j = 0; j <= jmax; j++) {
        __syncthreads();   // prior Wt/Ks/Vs reads done; first iter: Q stores visible
        // Load K (swizzled transpose) and V (natural)
        #pragma unroll
        for (int r = 0; r < 4; r++) {
            int f4 = tid + r * 256;      // 0..1023
            int k = f4 >> 4;             // 0..63
            int d = (f4 & 15) * 4;       // multiple of 4
            size_t g = base + (size_t)(j * 64 + k) * (3 * CC) + d;
            float4 kv = *(const float4*)&qkv[g + CC];
            int col = k ^ d;             // d&60 == d here
            Ks[(d + 0) * 64 + col] = kv.x;
            Ks[(d + 1) * 64 + col] = kv.y;
            Ks[(d + 2) * 64 + col] = kv.z;
            Ks[(d + 3) * 64 + col] = kv.w;
            float4 vv = *(const float4*)&qkv[g + 2 * CC];
            *(float4*)&Vs[k * 64 + d] = vv;
        }
        __syncthreads();

        // S = Q K^T  (8 q-rows x 4 k-cols per thread)
        u64 s2[8][2];
        #pragma unroll
        for (int i = 0; i < 8; i++) { s2[i][0] = 0ull; s2[i][1] = 0ull; }
        #pragma unroll 16
        for (int d = 0; d < 64; d++) {
            float4 a0 = *(const float4*)&Qs[d * 132 + ty * 8];
            float4 a1 = *(const float4*)&Qs[d * 132 + ty * 8 + 4];
            float4 bf = *(const float4*)&Ks[d * 64 + ((tx * 4) ^ (d & 60))];
            u64 b20 = pk2(bf.x, bf.y), b21 = pk2(bf.z, bf.w);
            float av[8] = {a0.x, a0.y, a0.z, a0.w, a1.x, a1.y, a1.z, a1.w};
            #pragma unroll
            for (int i = 0; i < 8; i++) {
                u64 a2 = pk2(av[i], av[i]);
                ffma2(s2[i][0], a2, b20);
                ffma2(s2[i][1], a2, b21);
            }
        }

        // softplus + causal mask + Wt store + per-thread rowsq
        const bool dg = (j >= 2 * qb);
        #pragma unroll
        for (int i = 0; i < 8; i++) {
            const int qg = qb * 128 + ty * 8 + i;
            float w[4];
            upk2(s2[i][0], w[0], w[1]);
            upk2(s2[i][1], w[2], w[3]);
            #pragma unroll
            for (int u = 0; u < 4; u++) {
                float sv = w[u];
                float e = __expf(-fabsf(sv));
                float v = fmaxf(sv, 0.f) + __logf(1.f + e);
                if (dg && (j * 64 + tx * 4 + u) > qg) v = 0.f;
                w[u] = v;
                prsq[i] = fmaf(v, v, prsq[i]);
            }
            *(float4*)&Wt[(ty * 8 + i) * 68 + tx * 4] = make_float4(w[0], w[1], w[2], w[3]);
        }
        __syncthreads();

        // O += W @ V  (8 q-rows x 4 d-cols per thread)
        #pragma unroll 8
        for (int k = 0; k < 64; k++) {
            float4 bf = *(const float4*)&Vs[k * 64 + tx * 4];
            u64 b20 = pk2(bf.x, bf.y), b21 = pk2(bf.z, bf.w);
            #pragma unroll
            for (int i = 0; i < 8; i++) {
                float a = Wt[(ty * 8 + i) * 68 + k];
                u64 a2 = pk2(a, a);
                ffma2(o2[i][0], a2, b20);
                ffma2(o2[i][1], a2, b21);
            }
        }
    }

    // Reduce rowsq across the 16 tx lanes, normalize, write out
    #pragma unroll
    for (int i = 0; i < 8; i++) {
        float p = prsq[i];
        p += __shfl_xor_sync(0xffffffffu, p, 1, 16);
        p += __shfl_xor_sync(0xffffffffu, p, 2, 16);
        p += __shfl_xor_sync(0xffffffffu, p, 4, 16);
        p += __shfl_xor_sync(0xffffffffu, p, 8, 16);
        float inv = rsqrtf(p);
        float c[4];
        upk2(o2[i][0], c[0], c[1]);
        upk2(o2[i][1], c[2], c[3]);
        const int qg = qb * 128 + ty * 8 + i;
        *(float4*)&att[(size_t)(b * TT + qg) * CC + h * HS + tx * 4] =
            make_float4(c[0] * inv, c[1] * inv, c[2] * inv, c[3] * inv);
    }
}

// ---------------------------------------------------------------------------
extern "C" void kernel_launch(void* const* d_in, const int* in_sizes, int n_in,
                              void* d_out, int out_size) {
    const float* x     = (const float*)d_in[0];  // [2,2048,1024]
    const float* Wqkv  = (const float*)d_in[1];  // [3072,1024]
    const float* Wproj = (const float*)d_in[2];  // [1024,1024]
    const float* bproj = (const float*)d_in[3];  // [1024]
    float* out = (float*)d_out;

    float *qkvp = nullptr, *attp = nullptr;
    cudaGetSymbolAddress((void**)&qkvp, g_qkv);
    cudaGetSymbolAddress((void**)&attp, g_att);

    cudaFuncSetAttribute(attn_kernel, cudaFuncAttributeMaxDynamicSharedMemorySize,
                         ATTN_SMEM_BYTES);

    // 1) QKV = x @ Wqkv^T : [4096,3072]
    gemm_nt<<<dim3((3 * CC) / 128, BT / 128), 256>>>(x, Wqkv, nullptr, qkvp, 3 * CC, CC, 0);

    // 2) attention (causal sp2norm) -> [4096,1024] in [B,T,C] layout
    attn_kernel<<<dim3(TT / 128, HH, BB), 256, ATTN_SMEM_BYTES>>>(qkvp, attp);

    // 3) out = att @ Wproj^T + b
    gemm_nt<<<dim3(CC / 128, BT / 128), 256>>>(attp, Wproj, bproj, out, CC, CC, 1);
}

// round 4
// speedup vs baseline: 2.2489x; 1.5436x over previous
#include <cuda_runtime.h>
#include <cuda_bf16.h>
#include <math.h>

#define BB 2
#define TT 2048
#define CC 1024
#define HH 16
#define HS 64
#define BT (BB*TT)   // 4096

typedef unsigned int u32;
typedef unsigned long long u64;

// ---------------------------------------------------------------------------
// Scratch (__device__ globals; no allocations allowed)
// ---------------------------------------------------------------------------
__device__ float g_qkv[(size_t)BT * 3 * CC];
__device__ float g_att[(size_t)BT * CC];
__device__ __align__(256) __nv_bfloat16 g_xhi[(size_t)BT * CC];
__device__ __align__(256) __nv_bfloat16 g_xlo[(size_t)BT * CC];
__device__ __align__(256) __nv_bfloat16 g_wqhi[(size_t)3 * CC * CC];
__device__ __align__(256) __nv_bfloat16 g_wqlo[(size_t)3 * CC * CC];
__device__ __align__(256) __nv_bfloat16 g_wphi[(size_t)CC * CC];
__device__ __align__(256) __nv_bfloat16 g_wplo[(size_t)CC * CC];
__device__ __align__(256) __nv_bfloat16 g_ahi[(size_t)BT * CC];
__device__ __align__(256) __nv_bfloat16 g_alo[(size_t)BT * CC];

// ---------------------------------------------------------------------------
// PTX helpers
// ---------------------------------------------------------------------------
__device__ __forceinline__ u32 s2u(const void* p) {
    u32 a;
    asm("{ .reg .u64 t; cvta.to.shared.u64 t, %1; cvt.u32.u64 %0, t; }"
        : "=r"(a) : "l"(p));
    return a;
}
__device__ __forceinline__ void cpa16(u32 dst, const void* src) {
    asm volatile("cp.async.cg.shared.global [%0], [%1], 16;" :: "r"(dst), "l"(src));
}
__device__ __forceinline__ void ldsm4(u32* r, u32 addr) {
    asm volatile("ldmatrix.sync.aligned.m8n8.x4.shared.b16 {%0,%1,%2,%3}, [%4];"
                 : "=r"(r[0]), "=r"(r[1]), "=r"(r[2]), "=r"(r[3]) : "r"(addr));
}
__device__ __forceinline__ void ldsm2(u32* r, u32 addr) {
    asm volatile("ldmatrix.sync.aligned.m8n8.x2.shared.b16 {%0,%1}, [%2];"
                 : "=r"(r[0]), "=r"(r[1]) : "r"(addr));
}
__device__ __forceinline__ void mma16816(float* d, const u32* a, const u32* b) {
    asm volatile(
        "mma.sync.aligned.m16n8k16.row.col.f32.bf16.bf16.f32 "
        "{%0,%1,%2,%3}, {%4,%5,%6,%7}, {%8,%9}, {%0,%1,%2,%3};"
        : "+f"(d[0]), "+f"(d[1]), "+f"(d[2]), "+f"(d[3])
        : "r"(a[0]), "r"(a[1]), "r"(a[2]), "r"(a[3]), "r"(b[0]), "r"(b[1]));
}

// f32x2 helpers (SIMT attention)
__device__ __forceinline__ u64 pk2(float x, float y) {
    u64 r; asm("mov.b64 %0, {%1,%2};" : "=l"(r) : "f"(x), "f"(y)); return r;
}
__device__ __forceinline__ void upk2(u64 v, float& x, float& y) {
    asm("mov.b64 {%0,%1}, %2;" : "=f"(x), "=f"(y) : "l"(v));
}
__device__ __forceinline__ void ffma2(u64& d, u64 a, u64 b) {
    asm("fma.rn.f32x2 %0, %1, %2, %0;" : "+l"(d) : "l"(a), "l"(b));
}

// ---------------------------------------------------------------------------
// fp32 -> bf16 hi/lo split
// ---------------------------------------------------------------------------
__global__ __launch_bounds__(256)
void split_bf16(const float4* __restrict__ src, uint2* __restrict__ hi,
                uint2* __restrict__ lo, int n4) {
    int i = blockIdx.x * blockDim.x + threadIdx.x;
    if (i >= n4) return;
    float4 v = src[i];
    float f[4] = {v.x, v.y, v.z, v.w};
    u32 h2[2], l2[2];
    #pragma unroll
    for (int p = 0; p < 2; p++) {
        u32 hw = 0, lw = 0;
        #pragma unroll
        for (int q = 0; q < 2; q++) {
            float val = f[p * 2 + q];
            __nv_bfloat16 hb = __float2bfloat16(val);
            float r = val - __bfloat162float(hb);
            __nv_bfloat16 lb = __float2bfloat16(r);
            hw |= (u32)__bfloat16_as_ushort(hb) << (16 * q);
            lw |= (u32)__bfloat16_as_ushort(lb) << (16 * q);
        }
        h2[p] = hw; l2[p] = lw;
    }
    hi[i] = make_uint2(h2[0], h2[1]);
    lo[i] = make_uint2(l2[0], l2[1]);
}

// ---------------------------------------------------------------------------
// HMMA GEMM: C[M,N] = (Ahi+Alo)[M,K] @ (Whi+Wlo)[N,K]^T (+bias)
// 128x128x32 CTA tile, 8 warps (2m x 4n), warp tile 64x32, m16n8k16 bf16.
// Double-buffered cp.async. Smem tile layout: rows of 32 bf16 (4x16B chunks),
// XOR swizzle chunk' = c ^ ((r>>1)&3) -> conflict-free ldmatrix.
// Stage (32KB): Ah[8K] Al[8K] Wh[8K] Wl[8K]; 2 stages = 64KB dynamic smem.
// ---------------------------------------------------------------------------
#define GM_SMEM_BYTES (2 * 32768)

__device__ __forceinline__ u32 sw_off(int r, int c) {
    return (u32)(((r << 2) + (c ^ ((r >> 1) & 3))) << 4);
}

__device__ __forceinline__ void load_tile(
    u32 sbuf, int tid,
    const __nv_bfloat16* __restrict__ Ah, const __nv_bfloat16* __restrict__ Al,
    const __nv_bfloat16* __restrict__ Wh, const __nv_bfloat16* __restrict__ Wl,
    int bm, int bn, int K, int k0)
{
    #pragma unroll
    for (int q = 0; q < 2; q++) {
        int idx = tid + q * 256;      // 0..511
        int r = idx >> 2;             // 0..127
        int c = idx & 3;              // 0..3 (16B chunk = 8 bf16)
        u32 so = sw_off(r, c);
        size_t ga = (size_t)(bm + r) * K + k0 + c * 8;
        size_t gw = (size_t)(bn + r) * K + k0 + c * 8;
        cpa16(sbuf +         so, Ah + ga);
        cpa16(sbuf +  8192 + so, Al + ga);
        cpa16(sbuf + 16384 + so, Wh + gw);
        cpa16(sbuf + 24576 + so, Wl + gw);
    }
    asm volatile("cp.async.commit_group;" ::: "memory");
}

__global__ __launch_bounds__(256, 1)
void gemm_mma(const __nv_bfloat16* __restrict__ Ahi, const __nv_bfloat16* __restrict__ Alo,
              const __nv_bfloat16* __restrict__ Whi, const __nv_bfloat16* __restrict__ Wlo,
              const float* __restrict__ bias, float* __restrict__ Cmat,
              int N, int K) {
    extern __shared__ char smem[];
    const u32 sb = s2u(smem);
    const int tid = threadIdx.x;
    const int wid = tid >> 5, lane = tid & 31;
    const int bm = blockIdx.y * 128, bn = blockIdx.x * 128;
    const int wm = (wid >> 2) * 64;       // warp m offset (0 or 64)
    const int wn = (wid & 3) * 32;        // warp n offset

    float acc[4][4][4];                   // [mi][nj][frag]
    #pragma unroll
    for (int i = 0; i < 4; i++)
        #pragma unroll
        for (int j = 0; j < 4; j++)
            #pragma unroll
            for (int u = 0; u < 4; u++) acc[i][j][u] = 0.f;

    const int NIT = K / 32;

    load_tile(sb, tid, Ahi, Alo, Whi, Wlo, bm, bn, K, 0);

    // ldmatrix lane-derived coordinates
    const int arow = lane & 15;           // A: row within 16
    const int akh  = lane >> 4;           // A: k-half (0/1)
    const int brow = lane & 7;            // B: row within 8
    const int bkh  = (lane >> 3) & 1;     // B: k-half (0/1)

    for (int it = 0; it < NIT; it++) {
        if (it + 1 < NIT) {
            load_tile(sb + ((it + 1) & 1) * 32768, tid,
                      Ahi, Alo, Whi, Wlo, bm, bn, K, (it + 1) * 32);
            asm volatile("cp.async.wait_group 1;" ::: "memory");
        } else {
            asm volatile("cp.async.wait_group 0;" ::: "memory");
        }
        __syncthreads();

        const u32 bb = sb + (it & 1) * 32768;
        #pragma unroll
        for (int kk2 = 0; kk2 < 4; kk2 += 2) {   // k-chunk base (0 -> k0, 2 -> k16)
            u32 ah[4][4], al[4][4];
            #pragma unroll
            for (int i = 0; i < 4; i++) {
                u32 off = sw_off(wm + i * 16 + arow, kk2 + akh);
                ldsm4(ah[i], bb + off);
                ldsm4(al[i], bb + 8192 + off);
            }
            u32 wh[4][2], wl[4][2];
            #pragma unroll
            for (int j = 0; j < 4; j++) {
                u32 off = sw_off(wn + j * 8 + brow, kk2 + bkh);
                ldsm2(wh[j], bb + 16384 + off);
                ldsm2(wl[j], bb + 24576 + off);
            }
            #pragma unroll
            for (int i = 0; i < 4; i++)
                #pragma unroll
                for (int j = 0; j < 4; j++) {
                    mma16816(acc[i][j], ah[i], wh[j]);
                    mma16816(acc[i][j], ah[i], wl[j]);
                    mma16816(acc[i][j], al[i], wh[j]);
                }
        }
        __syncthreads();
    }

    // Epilogue
    const int g = lane >> 2, tc = lane & 3;
    #pragma unroll
    for (int i = 0; i < 4; i++) {
        #pragma unroll
        for (int j = 0; j < 4; j++) {
            const int col = bn + wn + j * 8 + tc * 2;
            float b0 = 0.f, b1 = 0.f;
            if (bias) { b0 = bias[col]; b1 = bias[col + 1]; }
            const size_t r0 = (size_t)(bm + wm + i * 16 + g) * N + col;
            const size_t r1 = r0 + (size_t)8 * N;
            *(float2*)&Cmat[r0] = make_float2(acc[i][j][0] + b0, acc[i][j][1] + b1);
            *(float2*)&Cmat[r1] = make_float2(acc[i][j][2] + b0, acc[i][j][3] + b1);
        }
    }
}

// ---------------------------------------------------------------------------
// sp2norm attention (SIMT, unchanged from R2): Br=128, Bc=64, 256 thr
// ---------------------------------------------------------------------------
#define QS_SZ (64 * 132)
#define KS_SZ (64 * 64)
#define VS_SZ (64 * 64)
#define WT_SZ (128 * 68)
#define ATTN_SMEM_BYTES ((QS_SZ + KS_SZ + VS_SZ + WT_SZ) * 4)

__global__ __launch_bounds__(256, 2)
void attn_kernel(const float* __restrict__ qkv, float* __restrict__ att) {
    extern __shared__ float sm[];
    float* Qs = sm;
    float* Ks = Qs + QS_SZ;
    float* Vs = Ks + KS_SZ;
    float* Wt = Vs + VS_SZ;

    const int tid = threadIdx.x;
    const int tx = tid & 15, ty = tid >> 4;
    const int qb = gridDim.x - 1 - blockIdx.x;
    const int h = blockIdx.y, b = blockIdx.z;
    const size_t base = (size_t)b * TT * (3 * CC) + h * HS;

    #pragma unroll
    for (int r = 0; r < 8; r++) {
        int f4 = tid + r * 256;
        int q = f4 >> 4;
        int d = (f4 & 15) * 4;
        float4 v = *(const float4*)&qkv[base + (size_t)(qb * 128 + q) * (3 * CC) + d];
        Qs[(d + 0) * 132 + q] = v.x * 0.125f;
        Qs[(d + 1) * 132 + q] = v.y * 0.125f;
        Qs[(d + 2) * 132 + q] = v.z * 0.125f;
        Qs[(d + 3) * 132 + q] = v.w * 0.125f;
    }

    u64 o2[8][2];
    float prsq[8];
    #pragma unroll
    for (int i = 0; i < 8; i++) { o2[i][0] = 0ull; o2[i][1] = 0ull; prsq[i] = 0.f; }

    const int jmax = 2 * qb + 1;
    for (int j = 0; j <= jmax; j++) {
        __syncthreads();
        #pragma unroll
        for (int r = 0; r < 4; r++) {
            int f4 = tid + r * 256;
            int k = f4 >> 4;
            int d = (f4 & 15) * 4;
            size_t g = base + (size_t)(j * 64 + k) * (3 * CC) + d;
            float4 kv = *(const float4*)&qkv[g + CC];
            int col = k ^ d;
            Ks[(d + 0) * 64 + col] = kv.x;
            Ks[(d + 1) * 64 + col] = kv.y;
            Ks[(d + 2) * 64 + col] = kv.z;
            Ks[(d + 3) * 64 + col] = kv.w;
            float4 vv = *(const float4*)&qkv[g + 2 * CC];
            *(float4*)&Vs[k * 64 + d] = vv;
        }
        __syncthreads();

        u64 s2[8][2];
        #pragma unroll
        for (int i = 0; i < 8; i++) { s2[i][0] = 0ull; s2[i][1] = 0ull; }
        #pragma unroll 16
        for (int d = 0; d < 64; d++) {
            float4 a0 = *(const float4*)&Qs[d * 132 + ty * 8];
            float4 a1 = *(const float4*)&Qs[d * 132 + ty * 8 + 4];
            float4 bf = *(const float4*)&Ks[d * 64 + ((tx * 4) ^ (d & 60))];
            u64 b20 = pk2(bf.x, bf.y), b21 = pk2(bf.z, bf.w);
            float av[8] = {a0.x, a0.y, a0.z, a0.w, a1.x, a1.y, a1.z, a1.w};
            #pragma unroll
            for (int i = 0; i < 8; i++) {
                u64 a2 = pk2(av[i], av[i]);
                ffma2(s2[i][0], a2, b20);
                ffma2(s2[i][1], a2, b21);
            }
        }

        const bool dg = (j >= 2 * qb);
        #pragma unroll
        for (int i = 0; i < 8; i++) {
            const int qg = qb * 128 + ty * 8 + i;
            float w[4];
            upk2(s2[i][0], w[0], w[1]);
            upk2(s2[i][1], w[2], w[3]);
            #pragma unroll
            for (int u = 0; u < 4; u++) {
                float sv = w[u];
                float e = __expf(-fabsf(sv));
                float v = fmaxf(sv, 0.f) + __logf(1.f + e);
                if (dg && (j * 64 + tx * 4 + u) > qg) v = 0.f;
                w[u] = v;
                prsq[i] = fmaf(v, v, prsq[i]);
            }
            *(float4*)&Wt[(ty * 8 + i) * 68 + tx * 4] = make_float4(w[0], w[1], w[2], w[3]);
        }
        __syncthreads();

        #pragma unroll 8
        for (int k = 0; k < 64; k++) {
            float4 bf = *(const float4*)&Vs[k * 64 + tx * 4];
            u64 b20 = pk2(bf.x, bf.y), b21 = pk2(bf.z, bf.w);
            #pragma unroll
            for (int i = 0; i < 8; i++) {
                float a = Wt[(ty * 8 + i) * 68 + k];
                u64 a2 = pk2(a, a);
                ffma2(o2[i][0], a2, b20);
                ffma2(o2[i][1], a2, b21);
            }
        }
    }

    #pragma unroll
    for (int i = 0; i < 8; i++) {
        float p = prsq[i];
        p += __shfl_xor_sync(0xffffffffu, p, 1, 16);
        p += __shfl_xor_sync(0xffffffffu, p, 2, 16);
        p += __shfl_xor_sync(0xffffffffu, p, 4, 16);
        p += __shfl_xor_sync(0xffffffffu, p, 8, 16);
        float inv = rsqrtf(p);
        float c[4];
        upk2(o2[i][0], c[0], c[1]);
        upk2(o2[i][1], c[2], c[3]);
        const int qg = qb * 128 + ty * 8 + i;
        *(float4*)&att[(size_t)(b * TT + qg) * CC + h * HS + tx * 4] =
            make_float4(c[0] * inv, c[1] * inv, c[2] * inv, c[3] * inv);
    }
}

// ---------------------------------------------------------------------------
extern "C" void kernel_launch(void* const* d_in, const int* in_sizes, int n_in,
                              void* d_out, int out_size) {
    const float* x     = (const float*)d_in[0];
    const float* Wqkv  = (const float*)d_in[1];
    const float* Wproj = (const float*)d_in[2];
    const float* bproj = (const float*)d_in[3];
    float* out = (float*)d_out;

    float *qkvp, *attp;
    __nv_bfloat16 *xhi, *xlo, *wqhi, *wqlo, *wphi, *wplo, *ahi, *alo;
    cudaGetSymbolAddress((void**)&qkvp, g_qkv);
    cudaGetSymbolAddress((void**)&attp, g_att);
    cudaGetSymbolAddress((void**)&xhi, g_xhi);
    cudaGetSymbolAddress((void**)&xlo, g_xlo);
    cudaGetSymbolAddress((void**)&wqhi, g_wqhi);
    cudaGetSymbolAddress((void**)&wqlo, g_wqlo);
    cudaGetSymbolAddress((void**)&wphi, g_wphi);
    cudaGetSymbolAddress((void**)&wplo, g_wplo);
    cudaGetSymbolAddress((void**)&ahi, g_ahi);
    cudaGetSymbolAddress((void**)&alo, g_alo);

    cudaFuncSetAttribute(gemm_mma, cudaFuncAttributeMaxDynamicSharedMemorySize,
                         GM_SMEM_BYTES);
    cudaFuncSetAttribute(attn_kernel, cudaFuncAttributeMaxDynamicSharedMemorySize,
                         ATTN_SMEM_BYTES);

    int n4x = BT * CC / 4;
    int n4q = 3 * CC * CC / 4;
    int n4p = CC * CC / 4;
    split_bf16<<<(n4x + 255) / 256, 256>>>((const float4*)x, (uint2*)xhi, (uint2*)xlo, n4x);
    split_bf16<<<(n4q + 255) / 256, 256>>>((const float4*)Wqkv, (uint2*)wqhi, (uint2*)wqlo, n4q);
    split_bf16<<<(n4p + 255) / 256, 256>>>((const float4*)Wproj, (uint2*)wphi, (uint2*)wplo, n4p);

    // 1) QKV = x @ Wqkv^T : [4096,3072]
    gemm_mma<<<dim3((3 * CC) / 128, BT / 128), 256, GM_SMEM_BYTES>>>(
        xhi, xlo, wqhi, wqlo, nullptr, qkvp, 3 * CC, CC);

    // 2) attention (causal sp2norm) -> [4096,1024]
    attn_kernel<<<dim3(TT / 128, HH, BB), 256, ATTN_SMEM_BYTES>>>(qkvp, attp);

    // 3) split attention output, then out = att @ Wproj^T + b
    split_bf16<<<(n4x + 255) / 256, 256>>>((const float4*)attp, (uint2*)ahi, (uint2*)alo, n4x);
    gemm_mma<<<dim3(CC / 128, BT / 128), 256, GM_SMEM_BYTES>>>(
        ahi, alo, wphi, wplo, bproj, out, CC, CC);
}

// round 5
// speedup vs baseline: 3.5318x; 1.5705x over previous
#include <cuda_runtime.h>
#include <cuda_bf16.h>
#include <math.h>

#define BB 2
#define TT 2048
#define CC 1024
#define HH 16
#define BT (BB*TT)   // 4096

typedef unsigned int u32;
typedef unsigned long long u64;

// ---------------------------------------------------------------------------
// Scratch (__device__ globals; no allocations allowed)
// ---------------------------------------------------------------------------
__device__ __align__(256) __nv_bfloat16 g_xhi[(size_t)BT * CC];
__device__ __align__(256) __nv_bfloat16 g_xlo[(size_t)BT * CC];
__device__ __align__(256) __nv_bfloat16 g_wqhi[(size_t)3 * CC * CC];
__device__ __align__(256) __nv_bfloat16 g_wqlo[(size_t)3 * CC * CC];
__device__ __align__(256) __nv_bfloat16 g_wphi[(size_t)CC * CC];
__device__ __align__(256) __nv_bfloat16 g_wplo[(size_t)CC * CC];
__device__ __align__(256) __nv_bfloat16 g_qhi[(size_t)BT * 3 * CC];
__device__ __align__(256) __nv_bfloat16 g_qlo[(size_t)BT * 3 * CC];
__device__ __align__(256) __nv_bfloat16 g_ahi[(size_t)BT * CC];
__device__ __align__(256) __nv_bfloat16 g_alo[(size_t)BT * CC];

// ---------------------------------------------------------------------------
// PTX helpers
// ---------------------------------------------------------------------------
__device__ __forceinline__ u32 s2u(const void* p) {
    u32 a;
    asm("{ .reg .u64 t; cvta.to.shared.u64 t, %1; cvt.u32.u64 %0, t; }"
        : "=r"(a) : "l"(p));
    return a;
}
__device__ __forceinline__ void cpa16(u32 dst, const void* src) {
    asm volatile("cp.async.cg.shared.global [%0], [%1], 16;" :: "r"(dst), "l"(src));
}
__device__ __forceinline__ void ldsm4(u32* r, u32 addr) {
    asm volatile("ldmatrix.sync.aligned.m8n8.x4.shared.b16 {%0,%1,%2,%3}, [%4];"
                 : "=r"(r[0]), "=r"(r[1]), "=r"(r[2]), "=r"(r[3]) : "r"(addr));
}
__device__ __forceinline__ void ldsm4t(u32* r, u32 addr) {
    asm volatile("ldmatrix.sync.aligned.m8n8.x4.trans.shared.b16 {%0,%1,%2,%3}, [%4];"
                 : "=r"(r[0]), "=r"(r[1]), "=r"(r[2]), "=r"(r[3]) : "r"(addr));
}
__device__ __forceinline__ void ldsm2(u32* r, u32 addr) {
    asm volatile("ldmatrix.sync.aligned.m8n8.x2.shared.b16 {%0,%1}, [%2];"
                 : "=r"(r[0]), "=r"(r[1]) : "r"(addr));
}
__device__ __forceinline__ void mma16816(float* d, const u32* a, const u32* b) {
    asm volatile(
        "mma.sync.aligned.m16n8k16.row.col.f32.bf16.bf16.f32 "
        "{%0,%1,%2,%3}, {%4,%5,%6,%7}, {%8,%9}, {%0,%1,%2,%3};"
        : "+f"(d[0]), "+f"(d[1]), "+f"(d[2]), "+f"(d[3])
        : "r"(a[0]), "r"(a[1]), "r"(a[2]), "r"(a[3]), "r"(b[0]), "r"(b[1]));
}
// Split (a,b) fp32 pair into packed bf16 hi-word and residual lo-word.
__device__ __forceinline__ void split2(float a, float b, u32& hw, u32& lw) {
    asm("cvt.rn.bf16x2.f32 %0, %1, %2;" : "=r"(hw) : "f"(b), "f"(a));
    float ha = __uint_as_float(hw << 16);
    float hb = __uint_as_float(hw & 0xFFFF0000u);
    float la = a - ha, lb = b - hb;
    asm("cvt.rn.bf16x2.f32 %0, %1, %2;" : "=r"(lw) : "f"(lb), "f"(la));
}
// softplus: max(x,0) + ln(1+e^{-|x|}); ln via ln1.5 + deg-9 series in y=(2e-1)/3
__device__ __forceinline__ float softplus_f(float x) {
    float e = __expf(-fabsf(x));
    float y = fmaf(e, 0.6666666667f, -0.3333333333f);
    float q = 0.1111111111f;
    q = fmaf(q, y, -0.125f);
    q = fmaf(q, y, 0.1428571429f);
    q = fmaf(q, y, -0.1666666667f);
    q = fmaf(q, y, 0.2f);
    q = fmaf(q, y, -0.25f);
    q = fmaf(q, y, 0.3333333333f);
    q = fmaf(q, y, -0.5f);
    q = fmaf(q, y, 1.0f);
    return fmaxf(x, 0.f) + fmaf(q, y, 0.4054651081f);
}

// ---------------------------------------------------------------------------
// fp32 -> bf16 hi/lo split kernel
// ---------------------------------------------------------------------------
__global__ __launch_bounds__(256)
void split_bf16(const float4* __restrict__ src, uint2* __restrict__ hi,
                uint2* __restrict__ lo, int n4) {
    int i = blockIdx.x * blockDim.x + threadIdx.x;
    if (i >= n4) return;
    float4 v = src[i];
    u32 h0, l0, h1, l1;
    split2(v.x, v.y, h0, l0);
    split2(v.z, v.w, h1, l1);
    hi[i] = make_uint2(h0, h1);
    lo[i] = make_uint2(l0, l1);
}

// ---------------------------------------------------------------------------
// HMMA GEMM: C[M,N] = (Ahi+Alo)[M,K] @ (Whi+Wlo)[N,K]^T
// 128x128x32 tile, 8 warps, 3-stage cp.async pipeline.
// Epilogue: fp32+bias (Cf != null) or bf16 hi/lo split (Oh/Ol).
// ---------------------------------------------------------------------------
#define GM_STAGE 32768
#define GM_SMEM_BYTES (3 * GM_STAGE)

__device__ __forceinline__ u32 sw_off(int r, int c) {
    return (u32)(((r << 2) + (c ^ ((r >> 1) & 3))) << 4);
}

__device__ __forceinline__ void load_tile_g(
    u32 sbuf, int tid,
    const __nv_bfloat16* __restrict__ Ah, const __nv_bfloat16* __restrict__ Al,
    const __nv_bfloat16* __restrict__ Wh, const __nv_bfloat16* __restrict__ Wl,
    int bm, int bn, int K, int k0)
{
    #pragma unroll
    for (int q = 0; q < 2; q++) {
        int idx = tid + q * 256;
        int r = idx >> 2;
        int c = idx & 3;
        u32 so = sw_off(r, c);
        size_t ga = (size_t)(bm + r) * K + k0 + c * 8;
        size_t gw = (size_t)(bn + r) * K + k0 + c * 8;
        cpa16(sbuf +         so, Ah + ga);
        cpa16(sbuf +  8192 + so, Al + ga);
        cpa16(sbuf + 16384 + so, Wh + gw);
        cpa16(sbuf + 24576 + so, Wl + gw);
    }
}

__global__ __launch_bounds__(256, 1)
void gemm_mma(const __nv_bfloat16* __restrict__ Ahi, const __nv_bfloat16* __restrict__ Alo,
              const __nv_bfloat16* __restrict__ Whi, const __nv_bfloat16* __restrict__ Wlo,
              const float* __restrict__ bias, float* __restrict__ Cf,
              __nv_bfloat16* __restrict__ Oh, __nv_bfloat16* __restrict__ Ol,
              int N, int K) {
    extern __shared__ char smem[];
    const u32 sb = s2u(smem);
    const int tid = threadIdx.x;
    const int wid = tid >> 5, lane = tid & 31;
    const int bm = blockIdx.y * 128, bn = blockIdx.x * 128;
    const int wm = (wid >> 2) * 64;
    const int wn = (wid & 3) * 32;

    float acc[4][4][4];
    #pragma unroll
    for (int i = 0; i < 4; i++)
        #pragma unroll
        for (int j = 0; j < 4; j++)
            #pragma unroll
            for (int u = 0; u < 4; u++) acc[i][j][u] = 0.f;

    const int NIT = K / 32;

    load_tile_g(sb, tid, Ahi, Alo, Whi, Wlo, bm, bn, K, 0);
    asm volatile("cp.async.commit_group;" ::: "memory");
    load_tile_g(sb + GM_STAGE, tid, Ahi, Alo, Whi, Wlo, bm, bn, K, 32);
    asm volatile("cp.async.commit_group;" ::: "memory");

    const int arow = lane & 15;
    const int akh  = lane >> 4;
    const int brow = lane & 7;
    const int bkh  = (lane >> 3) & 1;

    int cs = 0;
    for (int it = 0; it < NIT; it++) {
        int pf = it + 2;
        if (pf < NIT) {
            int ps = cs + 2; if (ps >= 3) ps -= 3;
            load_tile_g(sb + ps * GM_STAGE, tid, Ahi, Alo, Whi, Wlo, bm, bn, K, pf * 32);
        }
        asm volatile("cp.async.commit_group;" ::: "memory");
        asm volatile("cp.async.wait_group 2;" ::: "memory");
        __syncthreads();

        const u32 bb = sb + cs * GM_STAGE;
        #pragma unroll
        for (int kk2 = 0; kk2 < 4; kk2 += 2) {
            u32 ah[4][4], al[4][4];
            #pragma unroll
            for (int i = 0; i < 4; i++) {
                u32 off = sw_off(wm + i * 16 + arow, kk2 + akh);
                ldsm4(ah[i], bb + off);
                ldsm4(al[i], bb + 8192 + off);
            }
            u32 wh[4][2], wl[4][2];
            #pragma unroll
            for (int j = 0; j < 4; j++) {
                u32 off = sw_off(wn + j * 8 + brow, kk2 + bkh);
                ldsm2(wh[j], bb + 16384 + off);
                ldsm2(wl[j], bb + 24576 + off);
            }
            #pragma unroll
            for (int i = 0; i < 4; i++)
                #pragma unroll
                for (int j = 0; j < 4; j++) {
                    mma16816(acc[i][j], ah[i], wh[j]);
                    mma16816(acc[i][j], ah[i], wl[j]);
                    mma16816(acc[i][j], al[i], wh[j]);
                }
        }
        __syncthreads();
        cs = (cs == 2) ? 0 : cs + 1;
    }

    const int g = lane >> 2, tc = lane & 3;
    #pragma unroll
    for (int i = 0; i < 4; i++) {
        #pragma unroll
        for (int j = 0; j < 4; j++) {
            const int col = bn + wn + j * 8 + tc * 2;
            const size_t r0 = (size_t)(bm + wm + i * 16 + g) * N + col;
            const size_t r1 = r0 + (size_t)8 * N;
            if (Cf) {
                float b0 = bias ? bias[col] : 0.f;
                float b1 = bias ? bias[col + 1] : 0.f;
                *(float2*)&Cf[r0] = make_float2(acc[i][j][0] + b0, acc[i][j][1] + b1);
                *(float2*)&Cf[r1] = make_float2(acc[i][j][2] + b0, acc[i][j][3] + b1);
            } else {
                u32 hw, lw;
                split2(acc[i][j][0], acc[i][j][1], hw, lw);
                *(u32*)&Oh[r0] = hw; *(u32*)&Ol[r0] = lw;
                split2(acc[i][j][2], acc[i][j][3], hw, lw);
                *(u32*)&Oh[r1] = hw; *(u32*)&Ol[r1] = lw;
            }
        }
    }
}

// ---------------------------------------------------------------------------
// HMMA sp2norm attention.
// CTA: 128 q-rows (tile qb) x head h x batch b; 8 warps x 16 rows.
// Per 64-key block j: S = Qhi*Khi + Qlo*Khi + Qhi*Klo (m16n8k16),
// softplus+mask in fp32, W->A-frags in regs (hi/lo split),
// O += Whi*Vhi + Wlo*Vhi + Whi*Vlo (V via ldmatrix.x4.trans).
// Q smem 32KB + 2x32KB KV double buffer = 96KB.
// ---------------------------------------------------------------------------
#define AT_QH 0
#define AT_QL 16384
#define AT_BUF 32768
#define AT_SMEM_BYTES (32768 + 2 * 32768)

__device__ __forceinline__ void load_kv_a(
    u32 dst, int tid, const __nv_bfloat16* __restrict__ qhi,
    const __nv_bfloat16* __restrict__ qlo, size_t kvbase)
{
    #pragma unroll
    for (int q = 0; q < 2; q++) {
        int slot = tid + q * 256;       // 0..511
        int r = slot >> 3;              // 0..63
        int c = slot & 7;               // 0..7
        u32 so = (u32)(r * 128 + ((c ^ (r & 7)) << 4));
        size_t gk = kvbase + (size_t)r * (3 * CC) + CC + c * 8;
        size_t gv = gk + CC;
        cpa16(dst +         so, qhi + gk);
        cpa16(dst +  8192 + so, qlo + gk);
        cpa16(dst + 16384 + so, qhi + gv);
        cpa16(dst + 24576 + so, qlo + gv);
    }
}

__global__ __launch_bounds__(256)
void attn_mma(const __nv_bfloat16* __restrict__ qhi, const __nv_bfloat16* __restrict__ qlo,
              __nv_bfloat16* __restrict__ ahi, __nv_bfloat16* __restrict__ alo) {
    extern __shared__ char smem[];
    const u32 sb = s2u(smem);
    const int tid = threadIdx.x;
    const int wid = tid >> 5, lane = tid & 31;
    const int g = lane >> 2, tc = lane & 3;
    const int qb = gridDim.x - 1 - blockIdx.x;
    const int h = blockIdx.y, b = blockIdx.z;

    const size_t qbase = ((size_t)(b * TT + qb * 128)) * (3 * CC) + h * 64;

    // Q tile loads (hi+lo): 128 rows x 8 chunks each
    #pragma unroll
    for (int q = 0; q < 4; q++) {
        int slot = tid + q * 256;       // 0..1023
        int r = slot >> 3;
        int c = slot & 7;
        u32 so = (u32)(r * 128 + ((c ^ (r & 7)) << 4));
        size_t gq = qbase + (size_t)r * (3 * CC) + c * 8;
        cpa16(sb + AT_QH + so, qhi + gq);
        cpa16(sb + AT_QL + so, qlo + gq);
    }
    // KV block 0 into buf0 (same commit group as Q)
    load_kv_a(sb + AT_BUF, tid, qhi, qlo, ((size_t)(b * TT)) * (3 * CC) + h * 64);
    asm volatile("cp.async.commit_group;" ::: "memory");
    // KV block 1 into buf1
    load_kv_a(sb + AT_BUF + 32768, tid, qhi, qlo,
              ((size_t)(b * TT + 64)) * (3 * CC) + h * 64);
    asm volatile("cp.async.commit_group;" ::: "memory");
    asm volatile("cp.async.wait_group 1;" ::: "memory");
    __syncthreads();

    // Q fragments (persist across j): 4 k-chunks x a0..a3, hi and lo
    u32 qh[4][4], ql[4][4];
    {
        const int row = 16 * wid + (lane & 15);
        const int ckb = lane >> 4;
        #pragma unroll
        for (int t = 0; t < 4; t++) {
            int ck = 2 * t + ckb;
            u32 off = (u32)(row * 128 + ((ck ^ (row & 7)) << 4));
            ldsm4(qh[t], sb + AT_QH + off);
            ldsm4(ql[t], sb + AT_QL + off);
        }
    }

    float o[8][4];
    #pragma unroll
    for (int v = 0; v < 8; v++)
        #pragma unroll
        for (int u = 0; u < 4; u++) o[v][u] = 0.f;
    float rsq0 = 0.f, rsq1 = 0.f;

    const int qg0 = qb * 128 + 16 * wid + g;
    const int jmax = 2 * qb + 1;

    for (int j = 0; j <= jmax; j++) {
        const u32 bb = sb + AT_BUF + (j & 1) * 32768;
        const bool dg = (j >= 2 * qb);
        // warps whose entire strip is masked in this block contribute nothing
        const bool act = !(dg && (j * 64 > qb * 128 + 16 * wid + 15));

        if (act) {
            // ---- S = Q K^T
            float s[8][4];
            #pragma unroll
            for (int v = 0; v < 8; v++)
                #pragma unroll
                for (int u = 0; u < 4; u++) s[v][u] = 0.f;

            const int rowK = (lane & 7) + ((lane >> 4) << 3);
            const int ckK  = (lane >> 3) & 1;
            #pragma unroll
            for (int t = 0; t < 4; t++) {
                #pragma unroll
                for (int u = 0; u < 4; u++) {
                    int rK = 16 * u + rowK;
                    int ck = 2 * t + ckK;
                    u32 off = (u32)(rK * 128 + ((ck ^ (rK & 7)) << 4));
                    u32 kh[4], kl[4];
                    ldsm4(kh, bb + off);
                    ldsm4(kl, bb + 8192 + off);
                    mma16816(s[2*u],   qh[t], kh);
                    mma16816(s[2*u],   ql[t], kh);
                    mma16816(s[2*u],   qh[t], kl);
                    mma16816(s[2*u+1], qh[t], kh + 2);
                    mma16816(s[2*u+1], ql[t], kh + 2);
                    mma16816(s[2*u+1], qh[t], kl + 2);
                }
            }

            // ---- softplus + mask + pack W, then O += W V
            const int rowVb = (lane & 7) + (((lane >> 3) & 1) << 3);
            const int cvb = lane >> 4;
            #pragma unroll
            for (int t = 0; t < 4; t++) {
                float w0 = softplus_f(s[2*t][0]   * 0.125f);
                float w1 = softplus_f(s[2*t][1]   * 0.125f);
                float w2 = softplus_f(s[2*t][2]   * 0.125f);
                float w3 = softplus_f(s[2*t][3]   * 0.125f);
                float w4 = softplus_f(s[2*t+1][0] * 0.125f);
                float w5 = softplus_f(s[2*t+1][1] * 0.125f);
                float w6 = softplus_f(s[2*t+1][2] * 0.125f);
                float w7 = softplus_f(s[2*t+1][3] * 0.125f);
                if (dg) {
                    int kg = j * 64 + 16 * t + 2 * tc;
                    int q0 = qg0, q1 = qg0 + 8;
                    if (kg     > q0) w0 = 0.f;
                    if (kg + 1 > q0) w1 = 0.f;
                    if (kg     > q1) w2 = 0.f;
                    if (kg + 1 > q1) w3 = 0.f;
                    if (kg + 8 > q0) w4 = 0.f;
                    if (kg + 9 > q0) w5 = 0.f;
                    if (kg + 8 > q1) w6 = 0.f;
                    if (kg + 9 > q1) w7 = 0.f;
                }
                rsq0 = fmaf(w0, w0, rsq0); rsq0 = fmaf(w1, w1, rsq0);
                rsq0 = fmaf(w4, w4, rsq0); rsq0 = fmaf(w5, w5, rsq0);
                rsq1 = fmaf(w2, w2, rsq1); rsq1 = fmaf(w3, w3, rsq1);
                rsq1 = fmaf(w6, w6, rsq1); rsq1 = fmaf(w7, w7, rsq1);

                u32 wh[4], wl[4];
                split2(w0, w1, wh[0], wl[0]);
                split2(w2, w3, wh[1], wl[1]);
                split2(w4, w5, wh[2], wl[2]);
                split2(w6, w7, wh[3], wl[3]);

                const int rV = 16 * t + rowVb;
                #pragma unroll
                for (int v = 0; v < 4; v++) {
                    int cv = 2 * v + cvb;
                    u32 off = (u32)(rV * 128 + ((cv ^ (rV & 7)) << 4));
                    u32 vh[4], vl[4];
                    ldsm4t(vh, bb + 16384 + off);
                    ldsm4t(vl, bb + 24576 + off);
                    mma16816(o[2*v],   wh, vh);
                    mma16816(o[2*v],   wl, vh);
                    mma16816(o[2*v],   wh, vl);
                    mma16816(o[2*v+1], wh, vh + 2);
                    mma16816(o[2*v+1], wl, vh + 2);
                    mma16816(o[2*v+1], wh, vl + 2);
                }
            }
        }

        __syncthreads();   // all warps done reading buf (j&1)
        if (j + 2 <= jmax) {
            load_kv_a(sb + AT_BUF + (j & 1) * 32768, tid, qhi, qlo,
                      ((size_t)(b * TT + (j + 2) * 64)) * (3 * CC) + h * 64);
        }
        asm volatile("cp.async.commit_group;" ::: "memory");
        asm volatile("cp.async.wait_group 1;" ::: "memory");
        __syncthreads();   // buf (j+1) ready for everyone
    }

    // ---- normalize + write bf16 hi/lo
    rsq0 += __shfl_xor_sync(0xffffffffu, rsq0, 1);
    rsq0 += __shfl_xor_sync(0xffffffffu, rsq0, 2);
    rsq1 += __shfl_xor_sync(0xffffffffu, rsq1, 1);
    rsq1 += __shfl_xor_sync(0xffffffffu, rsq1, 2);
    const float inv0 = rsqrtf(rsq0);
    const float inv1 = rsqrtf(rsq1);

    const size_t obase = (size_t)(b * TT + qg0) * CC + h * 64 + 2 * tc;
    #pragma unroll
    for (int v = 0; v < 8; v++) {
        u32 hw, lw;
        split2(o[v][0] * inv0, o[v][1] * inv0, hw, lw);
        *(u32*)&ahi[obase + 8 * v] = hw;
        *(u32*)&alo[obase + 8 * v] = lw;
        split2(o[v][2] * inv1, o[v][3] * inv1, hw, lw);
        *(u32*)&ahi[obase + 8 * (size_t)CC + 8 * v] = hw;
        *(u32*)&alo[obase + 8 * (size_t)CC + 8 * v] = lw;
    }
}

// ---------------------------------------------------------------------------
extern "C" void kernel_launch(void* const* d_in, const int* in_sizes, int n_in,
                              void* d_out, int out_size) {
    const float* x     = (const float*)d_in[0];
    const float* Wqkv  = (const float*)d_in[1];
    const float* Wproj = (const float*)d_in[2];
    const float* bproj = (const float*)d_in[3];
    float* out = (float*)d_out;

    __nv_bfloat16 *xhi, *xlo, *wqhi, *wqlo, *wphi, *wplo, *qhi, *qlo, *ahi, *alo;
    cudaGetSymbolAddress((void**)&xhi, g_xhi);
    cudaGetSymbolAddress((void**)&xlo, g_xlo);
    cudaGetSymbolAddress((void**)&wqhi, g_wqhi);
    cudaGetSymbolAddress((void**)&wqlo, g_wqlo);
    cudaGetSymbolAddress((void**)&wphi, g_wphi);
    cudaGetSymbolAddress((void**)&wplo, g_wplo);
    cudaGetSymbolAddress((void**)&qhi, g_qhi);
    cudaGetSymbolAddress((void**)&qlo, g_qlo);
    cudaGetSymbolAddress((void**)&ahi, g_ahi);
    cudaGetSymbolAddress((void**)&alo, g_alo);

    cudaFuncSetAttribute(gemm_mma, cudaFuncAttributeMaxDynamicSharedMemorySize,
                         GM_SMEM_BYTES);
    cudaFuncSetAttribute(attn_mma, cudaFuncAttributeMaxDynamicSharedMemorySize,
                         AT_SMEM_BYTES);

    int n4x = BT * CC / 4;
    int n4q = 3 * CC * CC / 4;
    int n4p = CC * CC / 4;
    split_bf16<<<(n4x + 255) / 256, 256>>>((const float4*)x, (uint2*)xhi, (uint2*)xlo, n4x);
    split_bf16<<<(n4q + 255) / 256, 256>>>((const float4*)Wqkv, (uint2*)wqhi, (uint2*)wqlo, n4q);
    split_bf16<<<(n4p + 255) / 256, 256>>>((const float4*)Wproj, (uint2*)wphi, (uint2*)wplo, n4p);

    // 1) QKV = x @ Wqkv^T -> bf16 hi/lo directly
    gemm_mma<<<dim3((3 * CC) / 128, BT / 128), 256, GM_SMEM_BYTES>>>(
        xhi, xlo, wqhi, wqlo, nullptr, nullptr, qhi, qlo, 3 * CC, CC);

    // 2) attention (causal sp2norm) -> bf16 hi/lo directly
    attn_mma<<<dim3(TT / 128, HH, BB), 256, AT_SMEM_BYTES>>>(qhi, qlo, ahi, alo);

    // 3) out = att @ Wproj^T + b (fp32)
    gemm_mma<<<dim3(CC / 128, BT / 128), 256, GM_SMEM_BYTES>>>(
        ahi, alo, wphi, wplo, bproj, out, nullptr, nullptr, CC, CC);
}

// round 6
// speedup vs baseline: 3.8392x; 1.0870x over previous
#include <cuda_runtime.h>
#include <cuda_bf16.h>
#include <math.h>

#define BB 2
#define TT 2048
#define CC 1024
#define HH 16
#define BT (BB*TT)   // 4096

typedef unsigned int u32;
typedef unsigned long long u64;

// ---------------------------------------------------------------------------
// Scratch (__device__ globals; no allocations allowed)
// ---------------------------------------------------------------------------
__device__ __align__(256) __nv_bfloat16 g_xhi[(size_t)BT * CC];
__device__ __align__(256) __nv_bfloat16 g_xlo[(size_t)BT * CC];
__device__ __align__(256) __nv_bfloat16 g_wqhi[(size_t)3 * CC * CC];
__device__ __align__(256) __nv_bfloat16 g_wqlo[(size_t)3 * CC * CC];
__device__ __align__(256) __nv_bfloat16 g_wphi[(size_t)CC * CC];
__device__ __align__(256) __nv_bfloat16 g_wplo[(size_t)CC * CC];
__device__ __align__(256) __nv_bfloat16 g_qhi[(size_t)BT * 3 * CC];
__device__ __align__(256) __nv_bfloat16 g_qlo[(size_t)BT * 3 * CC];
__device__ __align__(256) __nv_bfloat16 g_ahi[(size_t)BT * CC];
__device__ __align__(256) __nv_bfloat16 g_alo[(size_t)BT * CC];

// ---------------------------------------------------------------------------
// PTX helpers
// ---------------------------------------------------------------------------
__device__ __forceinline__ u32 s2u(const void* p) {
    u32 a;
    asm("{ .reg .u64 t; cvta.to.shared.u64 t, %1; cvt.u32.u64 %0, t; }"
        : "=r"(a) : "l"(p));
    return a;
}
__device__ __forceinline__ void cpa16(u32 dst, const void* src) {
    asm volatile("cp.async.cg.shared.global [%0], [%1], 16;" :: "r"(dst), "l"(src));
}
__device__ __forceinline__ void ldsm4(u32* r, u32 addr) {
    asm volatile("ldmatrix.sync.aligned.m8n8.x4.shared.b16 {%0,%1,%2,%3}, [%4];"
                 : "=r"(r[0]), "=r"(r[1]), "=r"(r[2]), "=r"(r[3]) : "r"(addr));
}
__device__ __forceinline__ void ldsm4t(u32* r, u32 addr) {
    asm volatile("ldmatrix.sync.aligned.m8n8.x4.trans.shared.b16 {%0,%1,%2,%3}, [%4];"
                 : "=r"(r[0]), "=r"(r[1]), "=r"(r[2]), "=r"(r[3]) : "r"(addr));
}
__device__ __forceinline__ void ldsm2(u32* r, u32 addr) {
    asm volatile("ldmatrix.sync.aligned.m8n8.x2.shared.b16 {%0,%1}, [%2];"
                 : "=r"(r[0]), "=r"(r[1]) : "r"(addr));
}
__device__ __forceinline__ void mma16816(float* d, const u32* a, const u32* b) {
    asm volatile(
        "mma.sync.aligned.m16n8k16.row.col.f32.bf16.bf16.f32 "
        "{%0,%1,%2,%3}, {%4,%5,%6,%7}, {%8,%9}, {%0,%1,%2,%3};"
        : "+f"(d[0]), "+f"(d[1]), "+f"(d[2]), "+f"(d[3])
        : "r"(a[0]), "r"(a[1]), "r"(a[2]), "r"(a[3]), "r"(b[0]), "r"(b[1]));
}
// Split (a,b) fp32 pair into packed bf16 hi-word and residual lo-word.
__device__ __forceinline__ void split2(float a, float b, u32& hw, u32& lw) {
    asm("cvt.rn.bf16x2.f32 %0, %1, %2;" : "=r"(hw) : "f"(b), "f"(a));
    float ha = __uint_as_float(hw << 16);
    float hb = __uint_as_float(hw & 0xFFFF0000u);
    float la = a - ha, lb = b - hb;
    asm("cvt.rn.bf16x2.f32 %0, %1, %2;" : "=r"(lw) : "f"(lb), "f"(la));
}
// softplus: max(x,0) + ln(1+e^{-|x|}); ln via ln1.5 + deg-9 series in y=(2e-1)/3
__device__ __forceinline__ float softplus_f(float x) {
    float e = __expf(-fabsf(x));
    float y = fmaf(e, 0.6666666667f, -0.3333333333f);
    float q = 0.1111111111f;
    q = fmaf(q, y, -0.125f);
    q = fmaf(q, y, 0.1428571429f);
    q = fmaf(q, y, -0.1666666667f);
    q = fmaf(q, y, 0.2f);
    q = fmaf(q, y, -0.25f);
    q = fmaf(q, y, 0.3333333333f);
    q = fmaf(q, y, -0.5f);
    q = fmaf(q, y, 1.0f);
    return fmaxf(x, 0.f) + fmaf(q, y, 0.4054651081f);
}

// ---------------------------------------------------------------------------
// fp32 -> bf16 hi/lo split kernel
// ---------------------------------------------------------------------------
__global__ __launch_bounds__(256)
void split_bf16(const float4* __restrict__ src, uint2* __restrict__ hi,
                uint2* __restrict__ lo, int n4) {
    int i = blockIdx.x * blockDim.x + threadIdx.x;
    if (i >= n4) return;
    float4 v = src[i];
    u32 h0, l0, h1, l1;
    split2(v.x, v.y, h0, l0);
    split2(v.z, v.w, h1, l1);
    hi[i] = make_uint2(h0, h1);
    lo[i] = make_uint2(l0, l1);
}

// ---------------------------------------------------------------------------
// HMMA GEMM: C[M,N] = (Ahi+Alo)[M,K] @ (Whi+Wlo)[N,K]^T
// 128x128x32 tile, 8 warps, DOUBLE buffer, ONE sync per iter, 2 CTAs/SM.
// ---------------------------------------------------------------------------
#define GM_STAGE 32768
#define GM_SMEM_BYTES (2 * GM_STAGE)

__device__ __forceinline__ u32 sw_off(int r, int c) {
    return (u32)(((r << 2) + (c ^ ((r >> 1) & 3))) << 4);
}

__device__ __forceinline__ void load_tile_g(
    u32 sbuf, int tid,
    const __nv_bfloat16* __restrict__ Ah, const __nv_bfloat16* __restrict__ Al,
    const __nv_bfloat16* __restrict__ Wh, const __nv_bfloat16* __restrict__ Wl,
    int bm, int bn, int K, int k0)
{
    #pragma unroll
    for (int q = 0; q < 2; q++) {
        int idx = tid + q * 256;
        int r = idx >> 2;
        int c = idx & 3;
        u32 so = sw_off(r, c);
        size_t ga = (size_t)(bm + r) * K + k0 + c * 8;
        size_t gw = (size_t)(bn + r) * K + k0 + c * 8;
        cpa16(sbuf +         so, Ah + ga);
        cpa16(sbuf +  8192 + so, Al + ga);
        cpa16(sbuf + 16384 + so, Wh + gw);
        cpa16(sbuf + 24576 + so, Wl + gw);
    }
    asm volatile("cp.async.commit_group;" ::: "memory");
}

__global__ __launch_bounds__(256, 2)
void gemm_mma(const __nv_bfloat16* __restrict__ Ahi, const __nv_bfloat16* __restrict__ Alo,
              const __nv_bfloat16* __restrict__ Whi, const __nv_bfloat16* __restrict__ Wlo,
              const float* __restrict__ bias, float* __restrict__ Cf,
              __nv_bfloat16* __restrict__ Oh, __nv_bfloat16* __restrict__ Ol,
              int N, int K) {
    extern __shared__ char smem[];
    const u32 sb = s2u(smem);
    const int tid = threadIdx.x;
    const int wid = tid >> 5, lane = tid & 31;
    const int bm = blockIdx.y * 128, bn = blockIdx.x * 128;
    const int wm = (wid >> 2) * 64;
    const int wn = (wid & 3) * 32;

    float acc[4][4][4];
    #pragma unroll
    for (int i = 0; i < 4; i++)
        #pragma unroll
        for (int j = 0; j < 4; j++)
            #pragma unroll
            for (int u = 0; u < 4; u++) acc[i][j][u] = 0.f;

    const int NIT = K / 32;

    load_tile_g(sb, tid, Ahi, Alo, Whi, Wlo, bm, bn, K, 0);

    const int arow = lane & 15;
    const int akh  = lane >> 4;
    const int brow = lane & 7;
    const int bkh  = (lane >> 3) & 1;

    for (int it = 0; it < NIT; it++) {
        asm volatile("cp.async.wait_group 0;" ::: "memory");
        __syncthreads();   // stage (it&1) ready AND all warps done with prev compute
        if (it + 1 < NIT) {
            load_tile_g(sb + ((it + 1) & 1) * GM_STAGE, tid,
                        Ahi, Alo, Whi, Wlo, bm, bn, K, (it + 1) * 32);
        }

        const u32 bb = sb + (it & 1) * GM_STAGE;
        #pragma unroll
        for (int kk2 = 0; kk2 < 4; kk2 += 2) {
            u32 ah[4][4], al[4][4];
            #pragma unroll
            for (int i = 0; i < 4; i++) {
                u32 off = sw_off(wm + i * 16 + arow, kk2 + akh);
                ldsm4(ah[i], bb + off);
                ldsm4(al[i], bb + 8192 + off);
            }
            u32 wh[4][2], wl[4][2];
            #pragma unroll
            for (int j = 0; j < 4; j++) {
                u32 off = sw_off(wn + j * 8 + brow, kk2 + bkh);
                ldsm2(wh[j], bb + 16384 + off);
                ldsm2(wl[j], bb + 24576 + off);
            }
            #pragma unroll
            for (int i = 0; i < 4; i++)
                #pragma unroll
                for (int j = 0; j < 4; j++) {
                    mma16816(acc[i][j], ah[i], wh[j]);
                    mma16816(acc[i][j], ah[i], wl[j]);
                    mma16816(acc[i][j], al[i], wh[j]);
                }
        }
    }

    const int g = lane >> 2, tc = lane & 3;
    #pragma unroll
    for (int i = 0; i < 4; i++) {
        #pragma unroll
        for (int j = 0; j < 4; j++) {
            const int col = bn + wn + j * 8 + tc * 2;
            const size_t r0 = (size_t)(bm + wm + i * 16 + g) * N + col;
            const size_t r1 = r0 + (size_t)8 * N;
            if (Cf) {
                float b0 = bias ? bias[col] : 0.f;
                float b1 = bias ? bias[col + 1] : 0.f;
                *(float2*)&Cf[r0] = make_float2(acc[i][j][0] + b0, acc[i][j][1] + b1);
                *(float2*)&Cf[r1] = make_float2(acc[i][j][2] + b0, acc[i][j][3] + b1);
            } else {
                u32 hw, lw;
                split2(acc[i][j][0], acc[i][j][1], hw, lw);
                *(u32*)&Oh[r0] = hw; *(u32*)&Ol[r0] = lw;
                split2(acc[i][j][2], acc[i][j][3], hw, lw);
                *(u32*)&Oh[r1] = hw; *(u32*)&Ol[r1] = lw;
            }
        }
    }
}

// ---------------------------------------------------------------------------
// HMMA sp2norm attention (structure as R5) + 2 CTAs/SM.
// ---------------------------------------------------------------------------
#define AT_QH 0
#define AT_QL 16384
#define AT_BUF 32768
#define AT_SMEM_BYTES (32768 + 2 * 32768)

__device__ __forceinline__ void load_kv_a(
    u32 dst, int tid, const __nv_bfloat16* __restrict__ qhi,
    const __nv_bfloat16* __restrict__ qlo, size_t kvbase)
{
    #pragma unroll
    for (int q = 0; q < 2; q++) {
        int slot = tid + q * 256;
        int r = slot >> 3;
        int c = slot & 7;
        u32 so = (u32)(r * 128 + ((c ^ (r & 7)) << 4));
        size_t gk = kvbase + (size_t)r * (3 * CC) + CC + c * 8;
        size_t gv = gk + CC;
        cpa16(dst +         so, qhi + gk);
        cpa16(dst +  8192 + so, qlo + gk);
        cpa16(dst + 16384 + so, qhi + gv);
        cpa16(dst + 24576 + so, qlo + gv);
    }
}

__global__ __launch_bounds__(256, 2)
void attn_mma(const __nv_bfloat16* __restrict__ qhi, const __nv_bfloat16* __restrict__ qlo,
              __nv_bfloat16* __restrict__ ahi, __nv_bfloat16* __restrict__ alo) {
    extern __shared__ char smem[];
    const u32 sb = s2u(smem);
    const int tid = threadIdx.x;
    const int wid = tid >> 5, lane = tid & 31;
    const int g = lane >> 2, tc = lane & 3;
    const int qb = gridDim.x - 1 - blockIdx.x;
    const int h = blockIdx.y, b = blockIdx.z;

    const size_t qbase = ((size_t)(b * TT + qb * 128)) * (3 * CC) + h * 64;

    #pragma unroll
    for (int q = 0; q < 4; q++) {
        int slot = tid + q * 256;
        int r = slot >> 3;
        int c = slot & 7;
        u32 so = (u32)(r * 128 + ((c ^ (r & 7)) << 4));
        size_t gq = qbase + (size_t)r * (3 * CC) + c * 8;
        cpa16(sb + AT_QH + so, qhi + gq);
        cpa16(sb + AT_QL + so, qlo + gq);
    }
    load_kv_a(sb + AT_BUF, tid, qhi, qlo, ((size_t)(b * TT)) * (3 * CC) + h * 64);
    asm volatile("cp.async.commit_group;" ::: "memory");
    load_kv_a(sb + AT_BUF + 32768, tid, qhi, qlo,
              ((size_t)(b * TT + 64)) * (3 * CC) + h * 64);
    asm volatile("cp.async.commit_group;" ::: "memory");
    asm volatile("cp.async.wait_group 1;" ::: "memory");
    __syncthreads();

    u32 qh[4][4], ql[4][4];
    {
        const int row = 16 * wid + (lane & 15);
        const int ckb = lane >> 4;
        #pragma unroll
        for (int t = 0; t < 4; t++) {
            int ck = 2 * t + ckb;
            u32 off = (u32)(row * 128 + ((ck ^ (row & 7)) << 4));
            ldsm4(qh[t], sb + AT_QH + off);
            ldsm4(ql[t], sb + AT_QL + off);
        }
    }

    float o[8][4];
    #pragma unroll
    for (int v = 0; v < 8; v++)
        #pragma unroll
        for (int u = 0; u < 4; u++) o[v][u] = 0.f;
    float rsq0 = 0.f, rsq1 = 0.f;

    const int qg0 = qb * 128 + 16 * wid + g;
    const int jmax = 2 * qb + 1;

    for (int j = 0; j <= jmax; j++) {
        const u32 bb = sb + AT_BUF + (j & 1) * 32768;
        const bool dg = (j >= 2 * qb);
        const bool act = !(dg && (j * 64 > qb * 128 + 16 * wid + 15));

        if (act) {
            float s[8][4];
            #pragma unroll
            for (int v = 0; v < 8; v++)
                #pragma unroll
                for (int u = 0; u < 4; u++) s[v][u] = 0.f;

            const int rowK = (lane & 7) + ((lane >> 4) << 3);
            const int ckK  = (lane >> 3) & 1;
            #pragma unroll
            for (int t = 0; t < 4; t++) {
                #pragma unroll
                for (int u = 0; u < 4; u++) {
                    int rK = 16 * u + rowK;
                    int ck = 2 * t + ckK;
                    u32 off = (u32)(rK * 128 + ((ck ^ (rK & 7)) << 4));
                    u32 kh[4], kl[4];
                    ldsm4(kh, bb + off);
                    ldsm4(kl, bb + 8192 + off);
                    mma16816(s[2*u],   qh[t], kh);
                    mma16816(s[2*u],   ql[t], kh);
                    mma16816(s[2*u],   qh[t], kl);
                    mma16816(s[2*u+1], qh[t], kh + 2);
                    mma16816(s[2*u+1], ql[t], kh + 2);
                    mma16816(s[2*u+1], qh[t], kl + 2);
                }
            }

            const int rowVb = (lane & 7) + (((lane >> 3) & 1) << 3);
            const int cvb = lane >> 4;
            #pragma unroll
            for (int t = 0; t < 4; t++) {
                float w0 = softplus_f(s[2*t][0]   * 0.125f);
                float w1 = softplus_f(s[2*t][1]   * 0.125f);
                float w2 = softplus_f(s[2*t][2]   * 0.125f);
                float w3 = softplus_f(s[2*t][3]   * 0.125f);
                float w4 = softplus_f(s[2*t+1][0] * 0.125f);
                float w5 = softplus_f(s[2*t+1][1] * 0.125f);
                float w6 = softplus_f(s[2*t+1][2] * 0.125f);
                float w7 = softplus_f(s[2*t+1][3] * 0.125f);
                if (dg) {
                    int kg = j * 64 + 16 * t + 2 * tc;
                    int q0 = qg0, q1 = qg0 + 8;
                    if (kg     > q0) w0 = 0.f;
                    if (kg + 1 > q0) w1 = 0.f;
                    if (kg     > q1) w2 = 0.f;
                    if (kg + 1 > q1) w3 = 0.f;
                    if (kg + 8 > q0) w4 = 0.f;
                    if (kg + 9 > q0) w5 = 0.f;
                    if (kg + 8 > q1) w6 = 0.f;
                    if (kg + 9 > q1) w7 = 0.f;
                }
                rsq0 = fmaf(w0, w0, rsq0); rsq0 = fmaf(w1, w1, rsq0);
                rsq0 = fmaf(w4, w4, rsq0); rsq0 = fmaf(w5, w5, rsq0);
                rsq1 = fmaf(w2, w2, rsq1); rsq1 = fmaf(w3, w3, rsq1);
                rsq1 = fmaf(w6, w6, rsq1); rsq1 = fmaf(w7, w7, rsq1);

                u32 wh[4], wl[4];
                split2(w0, w1, wh[0], wl[0]);
                split2(w2, w3, wh[1], wl[1]);
                split2(w4, w5, wh[2], wl[2]);
                split2(w6, w7, wh[3], wl[3]);

                const int rV = 16 * t + rowVb;
                #pragma unroll
                for (int v = 0; v < 4; v++) {
                    int cv = 2 * v + cvb;
                    u32 off = (u32)(rV * 128 + ((cv ^ (rV & 7)) << 4));
                    u32 vh[4], vl[4];
                    ldsm4t(vh, bb + 16384 + off);
                    ldsm4t(vl, bb + 24576 + off);
                    mma16816(o[2*v],   wh, vh);
                    mma16816(o[2*v],   wl, vh);
                    mma16816(o[2*v],   wh, vl);
                    mma16816(o[2*v+1], wh, vh + 2);
                    mma16816(o[2*v+1], wl, vh + 2);
                    mma16816(o[2*v+1], wh, vl + 2);
                }
            }
        }

        __syncthreads();
        if (j + 2 <= jmax) {
            load_kv_a(sb + AT_BUF + (j & 1) * 32768, tid, qhi, qlo,
                      ((size_t)(b * TT + (j + 2) * 64)) * (3 * CC) + h * 64);
        }
        asm volatile("cp.async.commit_group;" ::: "memory");
        asm volatile("cp.async.wait_group 1;" ::: "memory");
        __syncthreads();
    }

    rsq0 += __shfl_xor_sync(0xffffffffu, rsq0, 1);
    rsq0 += __shfl_xor_sync(0xffffffffu, rsq0, 2);
    rsq1 += __shfl_xor_sync(0xffffffffu, rsq1, 1);
    rsq1 += __shfl_xor_sync(0xffffffffu, rsq1, 2);
    const float inv0 = rsqrtf(rsq0);
    const float inv1 = rsqrtf(rsq1);

    const size_t obase = (size_t)(b * TT + qg0) * CC + h * 64 + 2 * tc;
    #pragma unroll
    for (int v = 0; v < 8; v++) {
        u32 hw, lw;
        split2(o[v][0] * inv0, o[v][1] * inv0, hw, lw);
        *(u32*)&ahi[obase + 8 * v] = hw;
        *(u32*)&alo[obase + 8 * v] = lw;
        split2(o[v][2] * inv1, o[v][3] * inv1, hw, lw);
        *(u32*)&ahi[obase + 8 * (size_t)CC + 8 * v] = hw;
        *(u32*)&alo[obase + 8 * (size_t)CC + 8 * v] = lw;
    }
}

// ---------------------------------------------------------------------------
extern "C" void kernel_launch(void* const* d_in, const int* in_sizes, int n_in,
                              void* d_out, int out_size) {
    const float* x     = (const float*)d_in[0];
    const float* Wqkv  = (const float*)d_in[1];
    const float* Wproj = (const float*)d_in[2];
    const float* bproj = (const float*)d_in[3];
    float* out = (float*)d_out;

    __nv_bfloat16 *xhi, *xlo, *wqhi, *wqlo, *wphi, *wplo, *qhi, *qlo, *ahi, *alo;
    cudaGetSymbolAddress((void**)&xhi, g_xhi);
    cudaGetSymbolAddress((void**)&xlo, g_xlo);
    cudaGetSymbolAddress((void**)&wqhi, g_wqhi);
    cudaGetSymbolAddress((void**)&wqlo, g_wqlo);
    cudaGetSymbolAddress((void**)&wphi, g_wphi);
    cudaGetSymbolAddress((void**)&wplo, g_wplo);
    cudaGetSymbolAddress((void**)&qhi, g_qhi);
    cudaGetSymbolAddress((void**)&qlo, g_qlo);
    cudaGetSymbolAddress((void**)&ahi, g_ahi);
    cudaGetSymbolAddress((void**)&alo, g_alo);

    cudaFuncSetAttribute(gemm_mma, cudaFuncAttributeMaxDynamicSharedMemorySize,
                         GM_SMEM_BYTES);
    cudaFuncSetAttribute(attn_mma, cudaFuncAttributeMaxDynamicSharedMemorySize,
                         AT_SMEM_BYTES);

    int n4x = BT * CC / 4;
    int n4q = 3 * CC * CC / 4;
    int n4p = CC * CC / 4;
    split_bf16<<<(n4x + 255) / 256, 256>>>((const float4*)x, (uint2*)xhi, (uint2*)xlo, n4x);
    split_bf16<<<(n4q + 255) / 256, 256>>>((const float4*)Wqkv, (uint2*)wqhi, (uint2*)wqlo, n4q);
    split_bf16<<<(n4p + 255) / 256, 256>>>((const float4*)Wproj, (uint2*)wphi, (uint2*)wplo, n4p);

    // 1) QKV = x @ Wqkv^T -> bf16 hi/lo directly
    gemm_mma<<<dim3((3 * CC) / 128, BT / 128), 256, GM_SMEM_BYTES>>>(
        xhi, xlo, wqhi, wqlo, nullptr, nullptr, qhi, qlo, 3 * CC, CC);

    // 2) attention (causal sp2norm) -> bf16 hi/lo directly
    attn_mma<<<dim3(TT / 128, HH, BB), 256, AT_SMEM_BYTES>>>(qhi, qlo, ahi, alo);

    // 3) out = att @ Wproj^T + b (fp32)
    gemm_mma<<<dim3(CC / 128, BT / 128), 256, GM_SMEM_BYTES>>>(
        ahi, alo, wphi, wplo, bproj, out, nullptr, nullptr, CC, CC);
}